// round 1
// baseline (speedup 1.0000x reference)
#include <cuda_runtime.h>

#define BB 64
#define NN 512
#define DD 64
#define HH 4
#define CC 64
#define NEGS 0.2f

// Scratch (device globals - no runtime allocation allowed)
__device__ float g_h[BB*NN*HH*CC];     // [b][n][h][c]  33.5 MB
__device__ float g_x[BB*NN*DD];        // layer activations
__device__ float g_asrc[BB*HH*NN];     // [b][h][n]
__device__ float g_adst[BB*HH*NN];     // [b][h][n]

// ---------------------------------------------------------------------------
// Kernel 1: h = x @ W^T for one layer, tiled 64 rows x 64 cols (one head per
// block in y). Epilogue computes a_src/a_dst per node (dot of h-row with att
// vectors, reduced across the 16 column-threads via shfl).
// ---------------------------------------------------------------------------
__global__ __launch_bounds__(256) void k_lin(
    const float* __restrict__ x, const float* __restrict__ W,
    const float* __restrict__ attS, const float* __restrict__ attD)
{
    __shared__ float s_x[64][68];   // transposed [k][row]
    __shared__ float s_w[64][68];   // transposed [k][col]
    const int t    = threadIdx.x;
    const int row0 = blockIdx.x * 64;
    const int hh   = blockIdx.y;

    // Stage tiles, transposed so the compute loop uses float4 LDS.
    {
        const int li = t >> 2;      // 0..63 row/col
        const int c4 = t & 3;       // float4 column group
        const float4* x4 = (const float4*)x;
        const float4* w4 = (const float4*)W;
        #pragma unroll
        for (int q = 0; q < 4; q++) {
            int kc = c4 + q * 4;    // 0..15
            float4 v = x4[(row0 + li) * 16 + kc];
            s_x[kc*4+0][li] = v.x; s_x[kc*4+1][li] = v.y;
            s_x[kc*4+2][li] = v.z; s_x[kc*4+3][li] = v.w;
            float4 u = w4[(hh * 64 + li) * 16 + kc];
            s_w[kc*4+0][li] = u.x; s_w[kc*4+1][li] = u.y;
            s_w[kc*4+2][li] = u.z; s_w[kc*4+3][li] = u.w;
        }
    }
    __syncthreads();

    const int tx = t & 15, ty = t >> 4;   // tx: col/4, ty: row/4
    float acc[4][4] = {};
    #pragma unroll
    for (int k = 0; k < 64; k++) {
        float4 a = *(const float4*)&s_x[k][ty * 4];
        float4 b = *(const float4*)&s_w[k][tx * 4];
        float av[4] = {a.x, a.y, a.z, a.w};
        float bv[4] = {b.x, b.y, b.z, b.w};
        #pragma unroll
        for (int i = 0; i < 4; i++)
            #pragma unroll
            for (int c = 0; c < 4; c++)
                acc[i][c] += av[i] * bv[c];
    }

    // Write h [row][256] with col offset hh*64
    #pragma unroll
    for (int i = 0; i < 4; i++) {
        *(float4*)&g_h[(row0 + ty * 4 + i) * 256 + hh * 64 + tx * 4] =
            make_float4(acc[i][0], acc[i][1], acc[i][2], acc[i][3]);
    }

    // a_src / a_dst epilogue
    float aSv[4], aDv[4];
    #pragma unroll
    for (int c = 0; c < 4; c++) {
        aSv[c] = attS[hh * 64 + tx * 4 + c];
        aDv[c] = attD[hh * 64 + tx * 4 + c];
    }
    #pragma unroll
    for (int i = 0; i < 4; i++) {
        float ps = 0.f, pd = 0.f;
        #pragma unroll
        for (int c = 0; c < 4; c++) { ps += acc[i][c] * aSv[c]; pd += acc[i][c] * aDv[c]; }
        #pragma unroll
        for (int off = 8; off > 0; off >>= 1) {
            ps += __shfl_xor_sync(0xffffffffu, ps, off);
            pd += __shfl_xor_sync(0xffffffffu, pd, off);
        }
        if (tx == 0) {
            int ng = row0 + ty * 4 + i;
            int b = ng >> 9, n = ng & 511;
            g_asrc[(b * HH + hh) * NN + n] = ps;
            g_adst[(b * HH + hh) * NN + n] = pd;
        }
    }
}

// ---------------------------------------------------------------------------
// Kernel 2: fused softmax + aggregation + head-mean + bias + relu.
// Block = (b, i-tile of 128). 256 threads, microtile 4i x 8c.
// Phase A computes per-(h,i) softmax max & 1/sum over all 512 j.
// Phase B loops (head, j-tile of 64): stages h tile + alpha tile in smem,
// then accumulates the matmul. Epilogue: mean over heads, bias, relu -> g_x.
// ---------------------------------------------------------------------------
extern __shared__ float smem[];

__global__ void k_agg(const float* __restrict__ cb)
{
    float* s_asrc = smem;                           // [4][512]   2048 f
    float* s_adst = smem + 2048;                    // [4][128]    512 f
    float* s_m    = smem + 2560;                    //             512 f
    float* s_r    = smem + 3072;                    //             512 f
    float (*s_h)[68]  = (float(*)[68])(smem + 3584);   // [64][68]
    float (*s_w)[132] = (float(*)[132])(smem + 7936);  // [64][132]

    const int t  = threadIdx.x;
    const int b  = blockIdx.x;
    const int i0 = blockIdx.y * 128;

    // Load a_src for all heads (this batch)
    {
        const float4* src = (const float4*)(g_asrc + b * HH * NN);
        float4* dst = (float4*)s_asrc;
        dst[t]       = src[t];
        dst[t + 256] = src[t + 256];
    }
    __syncthreads();

    // Phase A: softmax stats, 2 (h,i) pairs per thread
    #pragma unroll
    for (int pp = 0; pp < 2; pp++) {
        int p  = t + pp * 256;
        int h  = p >> 7;
        int il = p & 127;
        float d = g_adst[(b * HH + h) * NN + i0 + il];
        s_adst[h * 128 + il] = d;
        const float* as = s_asrc + h * 512;
        float m = -1e30f;
        #pragma unroll 8
        for (int j = 0; j < 512; j++) {
            float e = d + as[j];
            e = fmaxf(e, NEGS * e);
            m = fmaxf(m, e);
        }
        float s = 0.f;
        #pragma unroll 8
        for (int j = 0; j < 512; j++) {
            float e = d + as[j];
            e = fmaxf(e, NEGS * e);
            s += __expf(e - m);
        }
        s_m[h * 128 + il] = m;
        s_r[h * 128 + il] = 1.0f / s;
    }

    const int tx = t & 7;    // c / 8
    const int ty = t >> 3;   // i / 4
    float acc[4][8] = {};

    for (int h = 0; h < HH; h++) {
        for (int jt = 0; jt < 8; jt++) {
            const int j0 = jt * 64;
            __syncthreads();
            // Stage h tile [64 j][64 c]
            {
                int jl = t >> 2, c4 = t & 3;
                const float4* hp =
                    (const float4*)(g_h + ((b * NN + j0 + jl) * HH + h) * CC);
                #pragma unroll
                for (int q = 0; q < 4; q++) {
                    float4 v = hp[c4 + q * 4];
                    *(float4*)&s_h[jl][(c4 + q * 4) * 4] = v;
                }
            }
            // Compute alpha tile [64 j][128 i]
            {
                int jl = t >> 2, il0 = (t & 3) * 32;
                float aj = s_asrc[h * 512 + j0 + jl];
                #pragma unroll 8
                for (int q = 0; q < 32; q++) {
                    int il = il0 + q;
                    float e = s_adst[h * 128 + il] + aj;
                    e = fmaxf(e, NEGS * e);
                    s_w[jl][il] = __expf(e - s_m[h * 128 + il]) * s_r[h * 128 + il];
                }
            }
            __syncthreads();
            #pragma unroll 4
            for (int jl = 0; jl < 64; jl++) {
                float4 wv = *(const float4*)&s_w[jl][ty * 4];
                float4 h0 = *(const float4*)&s_h[jl][tx * 8];
                float4 h1 = *(const float4*)&s_h[jl][tx * 8 + 4];
                float wa[4] = {wv.x, wv.y, wv.z, wv.w};
                float hb[8] = {h0.x, h0.y, h0.z, h0.w, h1.x, h1.y, h1.z, h1.w};
                #pragma unroll
                for (int i = 0; i < 4; i++)
                    #pragma unroll
                    for (int c = 0; c < 8; c++)
                        acc[i][c] += wa[i] * hb[c];
            }
        }
    }

    // Epilogue: head mean (x0.25) + bias + relu -> g_x
    float bias[8];
    #pragma unroll
    for (int c = 0; c < 8; c++) bias[c] = cb[tx * 8 + c];
    #pragma unroll
    for (int i = 0; i < 4; i++) {
        float v[8];
        #pragma unroll
        for (int c = 0; c < 8; c++)
            v[c] = fmaxf(acc[i][c] * 0.25f + bias[c], 0.f);
        float* xp = g_x + (b * NN + i0 + ty * 4 + i) * DD + tx * 8;
        *(float4*)xp       = make_float4(v[0], v[1], v[2], v[3]);
        *(float4*)(xp + 4) = make_float4(v[4], v[5], v[6], v[7]);
    }
}

// ---------------------------------------------------------------------------
// Kernel 3: node-mean pooling + readout linear. One block per batch element.
// ---------------------------------------------------------------------------
__global__ __launch_bounds__(256) void k_read(
    const float* __restrict__ rw, const float* __restrict__ rb,
    float* __restrict__ out)
{
    __shared__ float s_part[4][64];
    __shared__ float s_pool[64];
    const int t = threadIdx.x;
    const int b = blockIdx.x;
    const int c = t & 63, part = t >> 6;
    float s = 0.f;
    for (int i = part; i < NN; i += 4)
        s += g_x[(b * NN + i) * DD + c];
    s_part[part][c] = s;
    __syncthreads();
    if (t < 64)
        s_pool[t] = (s_part[0][t] + s_part[1][t] + s_part[2][t] + s_part[3][t])
                    * (1.0f / NN);
    __syncthreads();
    if (t < 64) {
        float a = rb[t];
        #pragma unroll 8
        for (int c2 = 0; c2 < 64; c2++)
            a += s_pool[c2] * rw[t * 64 + c2];
        out[b * 64 + t] = a;
    }
}

// ---------------------------------------------------------------------------
extern "C" void kernel_launch(void* const* d_in, const int* in_sizes, int n_in,
                              void* d_out, int out_size)
{
    const float* emb = (const float*)d_in[0];
    const float* lin = (const float*)d_in[1];
    const float* aS  = (const float*)d_in[2];
    const float* aD  = (const float*)d_in[3];
    const float* cb  = (const float*)d_in[4];
    const float* rw  = (const float*)d_in[5];
    const float* rb  = (const float*)d_in[6];
    float* out = (float*)d_out;

    float* gx = nullptr;
    cudaGetSymbolAddress((void**)&gx, g_x);
    cudaFuncSetAttribute(k_agg, cudaFuncAttributeMaxDynamicSharedMemorySize, 65536);

    for (int l = 0; l < 3; l++) {
        const float* xin = (l == 0) ? emb : gx;
        k_lin<<<dim3(512, 4), 256>>>(xin, lin + l * 256 * 64,
                                     aS + l * HH * CC, aD + l * HH * CC);
        k_agg<<<dim3(64, 4), 256, 65536>>>(cb + l * CC);
    }
    k_read<<<64, 256>>>(rw, rb, out);
}

// round 2
// speedup vs baseline: 1.4051x; 1.4051x over previous
#include <cuda_runtime.h>

#define BB 64
#define NN 512
#define DD 64
#define HH 4
#define CC 64
#define NEGS 0.2f

typedef unsigned long long ull;

// Scratch (device globals - no runtime allocation allowed)
__device__ float g_h[BB*NN*HH*CC];     // [b][n][h][c]
__device__ float g_x[BB*NN*DD];        // layer activations
__device__ float g_asrc[BB*HH*NN];     // [b][h][n]
__device__ float g_adst[BB*HH*NN];     // [b][h][n]

// ---- f32x2 helpers -------------------------------------------------------
__device__ __forceinline__ ull packdup(float a) {
    ull r; asm("mov.b64 %0, {%1, %1};" : "=l"(r) : "f"(a)); return r;
}
__device__ __forceinline__ ull pack2(float a, float b) {
    ull r; asm("mov.b64 %0, {%1, %2};" : "=l"(r) : "f"(a), "f"(b)); return r;
}
__device__ __forceinline__ void fma2(ull& d, ull a, ull b) {
    asm("fma.rn.f32x2 %0, %1, %2, %0;" : "+l"(d) : "l"(a), "l"(b));
}
__device__ __forceinline__ float2 unpack2(ull v) {
    float2 r; asm("mov.b64 {%0, %1}, %2;" : "=f"(r.x), "=f"(r.y) : "l"(v));
    return r;
}

// ---------------------------------------------------------------------------
// Kernel 1: h = x @ W^T for one layer, 64x64 tile, one head per blockIdx.y.
// Epilogue computes a_src/a_dst per node.
// ---------------------------------------------------------------------------
__global__ __launch_bounds__(256) void k_lin(
    const float* __restrict__ x, const float* __restrict__ W,
    const float* __restrict__ attS, const float* __restrict__ attD)
{
    __shared__ float s_x[64][68];   // transposed [k][row]
    __shared__ float s_w[64][68];   // transposed [k][col]
    const int t    = threadIdx.x;
    const int row0 = blockIdx.x * 64;
    const int hh   = blockIdx.y;

    {
        const int li = t >> 2;
        const int c4 = t & 3;
        const float4* x4 = (const float4*)x;
        const float4* w4 = (const float4*)W;
        #pragma unroll
        for (int q = 0; q < 4; q++) {
            int kc = c4 + q * 4;
            float4 v = x4[(row0 + li) * 16 + kc];
            s_x[kc*4+0][li] = v.x; s_x[kc*4+1][li] = v.y;
            s_x[kc*4+2][li] = v.z; s_x[kc*4+3][li] = v.w;
            float4 u = w4[(hh * 64 + li) * 16 + kc];
            s_w[kc*4+0][li] = u.x; s_w[kc*4+1][li] = u.y;
            s_w[kc*4+2][li] = u.z; s_w[kc*4+3][li] = u.w;
        }
    }
    __syncthreads();

    const int tx = t & 15, ty = t >> 4;
    float acc[4][4] = {};
    #pragma unroll
    for (int k = 0; k < 64; k++) {
        float4 a = *(const float4*)&s_x[k][ty * 4];
        float4 b = *(const float4*)&s_w[k][tx * 4];
        float av[4] = {a.x, a.y, a.z, a.w};
        float bv[4] = {b.x, b.y, b.z, b.w};
        #pragma unroll
        for (int i = 0; i < 4; i++)
            #pragma unroll
            for (int c = 0; c < 4; c++)
                acc[i][c] += av[i] * bv[c];
    }

    #pragma unroll
    for (int i = 0; i < 4; i++) {
        *(float4*)&g_h[(row0 + ty * 4 + i) * 256 + hh * 64 + tx * 4] =
            make_float4(acc[i][0], acc[i][1], acc[i][2], acc[i][3]);
    }

    float aSv[4], aDv[4];
    #pragma unroll
    for (int c = 0; c < 4; c++) {
        aSv[c] = attS[hh * 64 + tx * 4 + c];
        aDv[c] = attD[hh * 64 + tx * 4 + c];
    }
    #pragma unroll
    for (int i = 0; i < 4; i++) {
        float ps = 0.f, pd = 0.f;
        #pragma unroll
        for (int c = 0; c < 4; c++) { ps += acc[i][c] * aSv[c]; pd += acc[i][c] * aDv[c]; }
        #pragma unroll
        for (int off = 8; off > 0; off >>= 1) {
            ps += __shfl_xor_sync(0xffffffffu, ps, off);
            pd += __shfl_xor_sync(0xffffffffu, pd, off);
        }
        if (tx == 0) {
            int ng = row0 + ty * 4 + i;
            int b = ng >> 9, n = ng & 511;
            g_asrc[(b * HH + hh) * NN + n] = ps;
            g_adst[(b * HH + hh) * NN + n] = pd;
        }
    }
}

// ---------------------------------------------------------------------------
// Kernel 2 (rewritten): fused attention aggregation, no-max softmax with
// deferred normalization.
//   Block: 128 threads, tile 128 i x 64 c, grid (64 b, 4 i-tiles) = 256 blocks
//   -> 2 blocks/SM, single wave on 148 SMs.
//   Microtile 8i x 8c, f32x2 packed FMA accumulators.
//   Per head: for each 64-j tile, stage h tile + generate w=exp(lrelu(d+s))
//   tile (generator thread owns one i, accumulates den_i in a register),
//   then accumulate num[i,c] += w * h. Head fold: acc_tot += (0.25/den_i)*num.
// ---------------------------------------------------------------------------
extern __shared__ float smem[];

__global__ __launch_bounds__(128) void k_agg(const float* __restrict__ cb)
{
    float* s_asrc = smem;                              // [4][512]  2048 f
    float* s_adst = smem + 2048;                       // [4][128]   512 f
    float* s_den  = smem + 2560;                       //            128 f
    float (*s_h)[68]  = (float(*)[68])(smem + 2688);   // [64][68]  4352 f
    float (*s_w)[128] = (float(*)[128])(smem + 7040);  // [64][128] 8192 f
    // total 15232 floats = 60928 B

    const int t  = threadIdx.x;
    const int b  = blockIdx.x;
    const int i0 = blockIdx.y * 128;

    // Load a_src for all heads of this batch
    {
        const float4* src = (const float4*)(g_asrc + b * HH * NN);
        float4* dst = (float4*)s_asrc;
        dst[t]       = src[t];
        dst[t + 128] = src[t + 128];
        dst[t + 256] = src[t + 256];
        dst[t + 384] = src[t + 384];
    }
    // Load a_dst for this i-tile, all heads
    #pragma unroll
    for (int h = 0; h < HH; h++)
        s_adst[h * 128 + t] = g_adst[(b * HH + h) * NN + i0 + t];
    __syncthreads();

    const int tx = t & 7;     // c group (8 cols)
    const int ty = t >> 3;    // i group (8 rows)

    ull accT[32];             // [8 i][4 cpair]  final (normalized) accumulator
    ull accH[32];             // per-head numerator
    #pragma unroll
    for (int k = 0; k < 32; k++) { accT[k] = 0ull; accH[k] = 0ull; }

    for (int h = 0; h < HH; h++) {
        const float d_t = s_adst[h * 128 + t];   // generator's own i = t
        float den = 0.f;
        const float* asr = s_asrc + h * 512;

        for (int jt = 0; jt < 8; jt++) {
            const int j0 = jt * 64;
            __syncthreads();   // previous tile fully consumed

            // Stage h tile [64 j][64 c]; thread: jl = t>>1, 32-col half
            {
                const int jl = t >> 1;
                const int c0 = (t & 1) * 32;
                const float4* hp =
                    (const float4*)(g_h + ((b * NN + j0 + jl) * HH + h) * CC + c0);
                float4* dp = (float4*)&s_h[jl][c0];
                #pragma unroll
                for (int q = 0; q < 8; q++) dp[q] = hp[q];
            }
            // Generate w tile [64 j][128 i]; thread t owns column i = t
            #pragma unroll 4
            for (int jl = 0; jl < 64; jl++) {
                float e = d_t + asr[j0 + jl];
                e = fmaxf(e, NEGS * e);
                float w = __expf(e);
                s_w[jl][t] = w;
                den += w;
            }
            __syncthreads();

            // Accumulate: acc[i][c] += w[i] * h[c]
            #pragma unroll 2
            for (int jl = 0; jl < 64; jl++) {
                float4 A0 = *(const float4*)&s_w[jl][ty * 8];
                float4 A1 = *(const float4*)&s_w[jl][ty * 8 + 4];
                float4 H0 = *(const float4*)&s_h[jl][tx * 8];
                float4 H1 = *(const float4*)&s_h[jl][tx * 8 + 4];
                ull hp[4];
                hp[0] = pack2(H0.x, H0.y); hp[1] = pack2(H0.z, H0.w);
                hp[2] = pack2(H1.x, H1.y); hp[3] = pack2(H1.z, H1.w);
                float av[8] = {A0.x, A0.y, A0.z, A0.w, A1.x, A1.y, A1.z, A1.w};
                #pragma unroll
                for (int i = 0; i < 8; i++) {
                    ull ad = packdup(av[i]);
                    #pragma unroll
                    for (int c2 = 0; c2 < 4; c2++)
                        fma2(accH[i * 4 + c2], ad, hp[c2]);
                }
            }
        }

        // Publish denominators (generator thread t owns i = t)
        __syncthreads();
        s_den[t] = den;
        __syncthreads();

        // Head fold: accT += (0.25/den_i) * accH ; reset accH
        #pragma unroll
        for (int i = 0; i < 8; i++) {
            float sc = 0.25f * __frcp_rn(s_den[ty * 8 + i]);
            ull sd = packdup(sc);
            #pragma unroll
            for (int c2 = 0; c2 < 4; c2++) {
                fma2(accT[i * 4 + c2], sd, accH[i * 4 + c2]);
                accH[i * 4 + c2] = 0ull;
            }
        }
    }

    // Epilogue: bias + relu -> g_x
    float bias[8];
    #pragma unroll
    for (int c = 0; c < 8; c++) bias[c] = cb[tx * 8 + c];
    #pragma unroll
    for (int i = 0; i < 8; i++) {
        float v[8];
        #pragma unroll
        for (int c2 = 0; c2 < 4; c2++) {
            float2 f = unpack2(accT[i * 4 + c2]);
            v[c2 * 2 + 0] = fmaxf(f.x + bias[c2 * 2 + 0], 0.f);
            v[c2 * 2 + 1] = fmaxf(f.y + bias[c2 * 2 + 1], 0.f);
        }
        float* xp = g_x + (b * NN + i0 + ty * 8 + i) * DD + tx * 8;
        *(float4*)xp       = make_float4(v[0], v[1], v[2], v[3]);
        *(float4*)(xp + 4) = make_float4(v[4], v[5], v[6], v[7]);
    }
}

// ---------------------------------------------------------------------------
// Kernel 3: node-mean pooling + readout linear.
// ---------------------------------------------------------------------------
__global__ __launch_bounds__(256) void k_read(
    const float* __restrict__ rw, const float* __restrict__ rb,
    float* __restrict__ out)
{
    __shared__ float s_part[4][64];
    __shared__ float s_pool[64];
    const int t = threadIdx.x;
    const int b = blockIdx.x;
    const int c = t & 63, part = t >> 6;
    float s = 0.f;
    for (int i = part; i < NN; i += 4)
        s += g_x[(b * NN + i) * DD + c];
    s_part[part][c] = s;
    __syncthreads();
    if (t < 64)
        s_pool[t] = (s_part[0][t] + s_part[1][t] + s_part[2][t] + s_part[3][t])
                    * (1.0f / NN);
    __syncthreads();
    if (t < 64) {
        float a = rb[t];
        #pragma unroll 8
        for (int c2 = 0; c2 < 64; c2++)
            a += s_pool[c2] * rw[t * 64 + c2];
        out[b * 64 + t] = a;
    }
}

// ---------------------------------------------------------------------------
extern "C" void kernel_launch(void* const* d_in, const int* in_sizes, int n_in,
                              void* d_out, int out_size)
{
    const float* emb = (const float*)d_in[0];
    const float* lin = (const float*)d_in[1];
    const float* aS  = (const float*)d_in[2];
    const float* aD  = (const float*)d_in[3];
    const float* cb  = (const float*)d_in[4];
    const float* rw  = (const float*)d_in[5];
    const float* rb  = (const float*)d_in[6];
    float* out = (float*)d_out;

    float* gx = nullptr;
    cudaGetSymbolAddress((void**)&gx, g_x);
    cudaFuncSetAttribute(k_agg, cudaFuncAttributeMaxDynamicSharedMemorySize, 61440);

    for (int l = 0; l < 3; l++) {
        const float* xin = (l == 0) ? emb : gx;
        k_lin<<<dim3(512, 4), 256>>>(xin, lin + l * 256 * 64,
                                     aS + l * HH * CC, aD + l * HH * CC);
        k_agg<<<dim3(64, 4), 128, 60928>>>(cb + l * CC);
    }
    k_read<<<64, 256>>>(rw, rb, out);
}